// round 14
// baseline (speedup 1.0000x reference)
#include <cuda_runtime.h>
#include <cstdint>

// LogicGatedSNN: spikes = (membrane + x · (states > 50)^T + noise) >= threshold
// x: [8192] fp32 binary, states: [8192, 8192] fp32, out: [8192] fp32
//
// DRAM-bound 256 MiB single-pass stream. x packed once into a 1KiB bitmask
// (pre-kernel). CTA-per-row. R14 probe: 512 threads/CTA, VEC=4 — halves
// MLP_p1 (8->4) and CTAs/SM (8->4) so oe*MLP_p1 drops 64 -> 16 = Q_th,
// collapsing cross-CTA L1tex-queue completion spread to the ~1.10 floor
// (B300 spread model) while keeping warps/SM and outstanding loads identical.

#define IN_F   8192
#define OUT_F  8192
#define NTHR   512
#define NWARPS (NTHR / 32)                 // 16
#define VEC    (IN_F / 4 / NTHR)           // 4 float4 per thread
#define PTHR   256                         // pack kernel threads

// Packed x: word t (t in [0,256)) holds bits for slot t's 32 columns under the
// 256-slot layout: bit (4*j + c) = x[4*(j*256 + t) + c] != 0, j in [0,8).
// The 512-thread main kernel reads 16 bits from word (tid & 255):
// its 4 float4s are j = (tid>>8)*4 + 0..3 of slot (tid & 255).
__device__ unsigned g_xbits[PTHR];

__global__ __launch_bounds__(PTHR) void pack_x_kernel(const float* __restrict__ x)
{
    const int tid = threadIdx.x;
    const float4* __restrict__ x4 = reinterpret_cast<const float4*>(x);
    unsigned w = 0;
    #pragma unroll
    for (int j = 0; j < 8; ++j) {
        const float4 v = x4[j * PTHR + tid];
        unsigned nib = (v.x != 0.0f ? 1u : 0u)
                     | (v.y != 0.0f ? 2u : 0u)
                     | (v.z != 0.0f ? 4u : 0u)
                     | (v.w != 0.0f ? 8u : 0u);
        w |= nib << (4 * j);
    }
    g_xbits[tid] = w;
}

__global__ __launch_bounds__(NTHR) void snn_bits512_kernel(
    const float* __restrict__ states,   // [OUT_F, IN_F]
    const float* __restrict__ mem,      // [OUT_F]
    const float* __restrict__ thr,      // [OUT_F]
    const float* __restrict__ noise,    // [OUT_F]
    float* __restrict__ out)            // [OUT_F]
{
    __shared__ int wsum[NWARPS];

    const int tid  = threadIdx.x;
    const int slot = tid & (PTHR - 1);     // column slot in the 256-slot layout
    const int jhi  = (tid >> 8) * 4;       // first j handled by this thread

    const int row = blockIdx.x;
    const float4* __restrict__ s4 =
        reinterpret_cast<const float4*>(states + (size_t)row * IN_F);

    // 4 independent streaming LDG.128 per thread (same columns as slot's
    // j = jhi..jhi+3 in the 256-layout: index j*256 + slot).
    float4 s[VEC];
    #pragma unroll
    for (int j = 0; j < VEC; ++j)
        s[j] = __ldcs(&s4[(jhi + j) * PTHR + slot]);

    const unsigned X = g_xbits[slot] >> (4 * jhi);  // 16 relevant bits

    int cnt = 0;
    #pragma unroll
    for (int j = 0; j < VEC; ++j) {
        const unsigned nib = X >> (4 * j);
        cnt += (s[j].x > 50.0f) & (int)(nib & 1u);
        cnt += (s[j].y > 50.0f) & (int)((nib >> 1) & 1u);
        cnt += (s[j].z > 50.0f) & (int)((nib >> 2) & 1u);
        cnt += (s[j].w > 50.0f) & (int)((nib >> 3) & 1u);
    }

    // Warp reduce (int)
    #pragma unroll
    for (int off = 16; off > 0; off >>= 1)
        cnt += __shfl_xor_sync(0xffffffffu, cnt, off);

    if ((tid & 31) == 0) wsum[tid >> 5] = cnt;
    __syncthreads();

    // Cross-warp sum by warp 0 (16 lanes + 4 shfls)
    if (tid < 32) {
        int c = (tid < NWARPS) ? wsum[tid] : 0;
        #pragma unroll
        for (int off = 8; off > 0; off >>= 1)
            c += __shfl_xor_sync(0xffffffffu, c, off);
        if (tid == 0) {
            const float p = mem[row] + (float)c + noise[row];
            out[row] = (p >= thr[row]) ? 1.0f : 0.0f;
        }
    }
}

extern "C" void kernel_launch(void* const* d_in, const int* in_sizes, int n_in,
                              void* d_out, int out_size) {
    const float* x      = (const float*)d_in[0];  // spike_input [1, 8192]
    const float* states = (const float*)d_in[1];  // synapse_states [8192, 8192]
    const float* mem    = (const float*)d_in[2];  // membrane_potential [8192]
    const float* thr    = (const float*)d_in[3];  // adaptive_threshold [8192]
    const float* noise  = (const float*)d_in[4];  // noise [8192]
    float* out = (float*)d_out;                   // spikes [8192]

    pack_x_kernel<<<1, PTHR>>>(x);
    snn_bits512_kernel<<<OUT_F, NTHR>>>(states, mem, thr, noise, out);
}

// round 15
// speedup vs baseline: 1.0227x; 1.0227x over previous
#include <cuda_runtime.h>
#include <cstdint>

// LogicGatedSNN: spikes = (membrane + x · (states > 50)^T + noise) >= threshold
// x: [8192] fp32 binary, states: [8192, 8192] fp32, out: [8192] fp32
//
// FINAL (converged; best of 9 designs / 14 rounds; reproduced 43.49us x3):
// DRAM-bound 256 MiB single-pass stream at 6.4-6.5 TB/s — the path-
// independent LTS/DRAM ceiling at memory-bound DVFS clocks.
//  - x packed once into a 1KiB bitmask by a tiny pre-kernel: removes 256MB of
//    parasitic x re-read traffic (the decisive win: 72 -> 43.5us overall).
//  - Main kernel: CTA-per-row, 256 threads, 8 independent streaming LDG.128
//    per thread fronted before any compute. 256x8 is the measured optimum of
//    the (warps/SM x per-warp-MLP) surface: 512x4 (R14) and deep-pipe/low-occ
//    variants (R6/R7) both regress.
//  - Measured dead ends: persistent grid, PDL (both forms), software-flag
//    fusion, tail trims — all <= neutral vs the 2-kernel structure.

#define IN_F   8192
#define OUT_F  8192
#define NTHR   256
#define NWARPS (NTHR / 32)
#define VEC    (IN_F / 4 / NTHR)           // 8 float4 per thread

// Packed x: word t holds bits for thread-slot t's 32 columns.
// bit (4*j + c) = x[4*(j*NTHR + t) + c] != 0
__device__ unsigned g_xbits[NTHR];

__global__ __launch_bounds__(NTHR) void pack_x_kernel(const float* __restrict__ x)
{
    const int tid = threadIdx.x;
    const float4* __restrict__ x4 = reinterpret_cast<const float4*>(x);
    unsigned w = 0;
    #pragma unroll
    for (int j = 0; j < VEC; ++j) {
        const float4 v = x4[j * NTHR + tid];
        unsigned nib = (v.x != 0.0f ? 1u : 0u)
                     | (v.y != 0.0f ? 2u : 0u)
                     | (v.z != 0.0f ? 4u : 0u)
                     | (v.w != 0.0f ? 8u : 0u);
        w |= nib << (4 * j);
    }
    g_xbits[tid] = w;
}

__global__ __launch_bounds__(NTHR) void snn_bits_kernel(
    const float* __restrict__ states,   // [OUT_F, IN_F]
    const float* __restrict__ mem,      // [OUT_F]
    const float* __restrict__ thr,      // [OUT_F]
    const float* __restrict__ noise,    // [OUT_F]
    float* __restrict__ out)            // [OUT_F]
{
    __shared__ int wsum[NWARPS];

    const int tid = threadIdx.x;
    const int row = blockIdx.x;

    const float4* __restrict__ s4 =
        reinterpret_cast<const float4*>(states + (size_t)row * IN_F);

    // states row: 8 independent streaming LDG.128 per thread, issued up front
    float4 s[VEC];
    #pragma unroll
    for (int j = 0; j < VEC; ++j)
        s[j] = __ldcs(&s4[j * NTHR + tid]);

    const unsigned X = g_xbits[tid];     // 1KiB total, L1-hot

    int cnt = 0;
    #pragma unroll
    for (int j = 0; j < VEC; ++j) {
        const unsigned nib = X >> (4 * j);
        cnt += (s[j].x > 50.0f) & (int)(nib & 1u);
        cnt += (s[j].y > 50.0f) & (int)((nib >> 1) & 1u);
        cnt += (s[j].z > 50.0f) & (int)((nib >> 2) & 1u);
        cnt += (s[j].w > 50.0f) & (int)((nib >> 3) & 1u);
    }

    // Warp reduce (int)
    #pragma unroll
    for (int off = 16; off > 0; off >>= 1)
        cnt += __shfl_xor_sync(0xffffffffu, cnt, off);

    if ((tid & 31) == 0) wsum[tid >> 5] = cnt;
    __syncthreads();

    // Cross-warp sum in parallel by warp 0 (8 lanes + 3 shfls)
    if (tid < 32) {
        int c = (tid < NWARPS) ? wsum[tid] : 0;
        #pragma unroll
        for (int off = 4; off > 0; off >>= 1)
            c += __shfl_xor_sync(0xffffffffu, c, off);
        if (tid == 0) {
            const float p = mem[row] + (float)c + noise[row];
            out[row] = (p >= thr[row]) ? 1.0f : 0.0f;
        }
    }
}

extern "C" void kernel_launch(void* const* d_in, const int* in_sizes, int n_in,
                              void* d_out, int out_size) {
    const float* x      = (const float*)d_in[0];  // spike_input [1, 8192]
    const float* states = (const float*)d_in[1];  // synapse_states [8192, 8192]
    const float* mem    = (const float*)d_in[2];  // membrane_potential [8192]
    const float* thr    = (const float*)d_in[3];  // adaptive_threshold [8192]
    const float* noise  = (const float*)d_in[4];  // noise [8192]
    float* out = (float*)d_out;                   // spikes [8192]

    pack_x_kernel<<<1, NTHR>>>(x);
    snn_bits_kernel<<<OUT_F, NTHR>>>(states, mem, thr, noise, out);
}

// round 16
// speedup vs baseline: 1.0287x; 1.0059x over previous
#include <cuda_runtime.h>
#include <cstdint>

// LogicGatedSNN: spikes = (membrane + x · (states > 50)^T + noise) >= threshold
// x: [8192] fp32 binary, states: [8192, 8192] fp32, out: [8192] fp32
//
// FINAL (converged; best of 9 designs / 15 rounds; 43.49us reproduced x3,
// noise band +/-0.3us): DRAM-bound 256 MiB single-pass stream at 6.4-6.5 TB/s
// — the path-independent LTS/DRAM ceiling at memory-bound DVFS clocks.
// Traffic is at the floor (every 32B sector carries needed bits), bandwidth at
// the ceiling, and every neighboring design point measured worse:
//  - x packed once into a 1KiB bitmask by a tiny pre-kernel: removes 256MB of
//    parasitic x re-read traffic (the decisive win: 72 -> 43.5us overall).
//  - Main kernel: CTA-per-row, 256 threads, 8 independent streaming LDG.128
//    per thread fronted before any compute. 256x8 is the measured optimum of
//    the (warps/SM x per-warp-MLP) surface (512x4 and deep-pipe both regress).
//  - Measured dead ends: persistent grid, PDL (both forms), software-flag
//    fusion, tail trims — all <= neutral vs the 2-kernel structure.

#define IN_F   8192
#define OUT_F  8192
#define NTHR   256
#define NWARPS (NTHR / 32)
#define VEC    (IN_F / 4 / NTHR)           // 8 float4 per thread

// Packed x: word t holds bits for thread-slot t's 32 columns.
// bit (4*j + c) = x[4*(j*NTHR + t) + c] != 0
__device__ unsigned g_xbits[NTHR];

__global__ __launch_bounds__(NTHR) void pack_x_kernel(const float* __restrict__ x)
{
    const int tid = threadIdx.x;
    const float4* __restrict__ x4 = reinterpret_cast<const float4*>(x);
    unsigned w = 0;
    #pragma unroll
    for (int j = 0; j < VEC; ++j) {
        const float4 v = x4[j * NTHR + tid];
        unsigned nib = (v.x != 0.0f ? 1u : 0u)
                     | (v.y != 0.0f ? 2u : 0u)
                     | (v.z != 0.0f ? 4u : 0u)
                     | (v.w != 0.0f ? 8u : 0u);
        w |= nib << (4 * j);
    }
    g_xbits[tid] = w;
}

__global__ __launch_bounds__(NTHR) void snn_bits_kernel(
    const float* __restrict__ states,   // [OUT_F, IN_F]
    const float* __restrict__ mem,      // [OUT_F]
    const float* __restrict__ thr,      // [OUT_F]
    const float* __restrict__ noise,    // [OUT_F]
    float* __restrict__ out)            // [OUT_F]
{
    __shared__ int wsum[NWARPS];

    const int tid = threadIdx.x;
    const int row = blockIdx.x;

    const float4* __restrict__ s4 =
        reinterpret_cast<const float4*>(states + (size_t)row * IN_F);

    // states row: 8 independent streaming LDG.128 per thread, issued up front
    float4 s[VEC];
    #pragma unroll
    for (int j = 0; j < VEC; ++j)
        s[j] = __ldcs(&s4[j * NTHR + tid]);

    const unsigned X = g_xbits[tid];     // 1KiB total, L1-hot

    int cnt = 0;
    #pragma unroll
    for (int j = 0; j < VEC; ++j) {
        const unsigned nib = X >> (4 * j);
        cnt += (s[j].x > 50.0f) & (int)(nib & 1u);
        cnt += (s[j].y > 50.0f) & (int)((nib >> 1) & 1u);
        cnt += (s[j].z > 50.0f) & (int)((nib >> 2) & 1u);
        cnt += (s[j].w > 50.0f) & (int)((nib >> 3) & 1u);
    }

    // Warp reduce (int)
    #pragma unroll
    for (int off = 16; off > 0; off >>= 1)
        cnt += __shfl_xor_sync(0xffffffffu, cnt, off);

    if ((tid & 31) == 0) wsum[tid >> 5] = cnt;
    __syncthreads();

    // Cross-warp sum in parallel by warp 0 (8 lanes + 3 shfls)
    if (tid < 32) {
        int c = (tid < NWARPS) ? wsum[tid] : 0;
        #pragma unroll
        for (int off = 4; off > 0; off >>= 1)
            c += __shfl_xor_sync(0xffffffffu, c, off);
        if (tid == 0) {
            const float p = mem[row] + (float)c + noise[row];
            out[row] = (p >= thr[row]) ? 1.0f : 0.0f;
        }
    }
}

extern "C" void kernel_launch(void* const* d_in, const int* in_sizes, int n_in,
                              void* d_out, int out_size) {
    const float* x      = (const float*)d_in[0];  // spike_input [1, 8192]
    const float* states = (const float*)d_in[1];  // synapse_states [8192, 8192]
    const float* mem    = (const float*)d_in[2];  // membrane_potential [8192]
    const float* thr    = (const float*)d_in[3];  // adaptive_threshold [8192]
    const float* noise  = (const float*)d_in[4];  // noise [8192]
    float* out = (float*)d_out;                   // spikes [8192]

    pack_x_kernel<<<1, NTHR>>>(x);
    snn_bits_kernel<<<OUT_F, NTHR>>>(states, mem, thr, noise, out);
}